// round 13
// baseline (speedup 1.0000x reference)
#include <cuda_runtime.h>
#include <cuda_fp16.h>
#include <cstdint>
#include <math.h>

// Problem constants
#define HID   1024
#define LT    256
#define LI    2048
#define LTOT  2304
#define NHEAD 16
#define HD    64
#define MLPD  4096

// ---------------- scratch (device globals; no cudaMalloc allowed) ----------
__device__ float  g_mod[12288];
__device__ __half g_imgm[LI * HID];
__device__ __half g_txtm[LT * HID];
__device__ __half g_qkv_img[LI * 3 * HID];
__device__ __half g_qkv_txt[LT * 3 * HID];
__device__ __half g_q[NHEAD * LTOT * HD];
__device__ __half g_k[NHEAD * LTOT * HD];
__device__ __half g_v[NHEAD * LTOT * HD];
__device__ __half g_attn[LTOT * HID];
__device__ float  g_img2[LI * HID];
__device__ __half g_ln2[LI * HID];
__device__ __half g_mlp[LI * MLPD];
__device__ float  g_w2part[2 * LI * HID];
// transposed weights [N,K] (fp16)
__device__ __half g_wt_iqkv[3 * HID * HID];
__device__ __half g_wt_tqkv[3 * HID * HID];
__device__ __half g_wt_proj[HID * HID];
__device__ __half g_wt_w1[MLPD * HID];
__device__ __half g_wt_w2[HID * MLPD];

// ---------------- PTX helpers ----------------------------------------------
__device__ __forceinline__ uint32_t smem_u32(const void* p) {
    uint32_t a;
    asm("{ .reg .u64 t; cvta.to.shared.u64 t, %1; cvt.u32.u64 %0, t; }" : "=r"(a) : "l"(p));
    return a;
}
#define CP_ASYNC16(dst, src) \
    asm volatile("cp.async.cg.shared.global [%0], [%1], 16;" :: "r"(dst), "l"(src))
#define CP_COMMIT() asm volatile("cp.async.commit_group;")
#define CP_WAIT(n)  asm volatile("cp.async.wait_group %0;" :: "n"(n))

#define LDSM_X4(r, a)                                                          \
    asm volatile("ldmatrix.sync.aligned.m8n8.x4.shared.b16 {%0,%1,%2,%3}, [%4];" \
        : "=r"((r)[0]), "=r"((r)[1]), "=r"((r)[2]), "=r"((r)[3]) : "r"(a))

#define LDSM_X4_T(r, a)                                                        \
    asm volatile("ldmatrix.sync.aligned.m8n8.x4.trans.shared.b16 {%0,%1,%2,%3}, [%4];" \
        : "=r"((r)[0]), "=r"((r)[1]), "=r"((r)[2]), "=r"((r)[3]) : "r"(a))

// D += A(f16) * B(f16), fp32 accumulate, m16n8k16
#define MMA_F16(d, a, b0, b1)                                                  \
    asm volatile("mma.sync.aligned.m16n8k16.row.col.f32.f16.f16.f32 "          \
        "{%0,%1,%2,%3}, {%4,%5,%6,%7}, {%8,%9}, {%0,%1,%2,%3};"                \
        : "+f"((d)[0]), "+f"((d)[1]), "+f"((d)[2]), "+f"((d)[3])               \
        : "r"((a)[0]), "r"((a)[1]), "r"((a)[2]), "r"((a)[3]),                  \
          "r"(b0), "r"(b1))

// ---------------- merged weight transpose + f16: W[K,N] -> WT[N,K] ---------
__global__ void transpose_all(
    const float* __restrict__ iqkvw, const float* __restrict__ tqkvw,
    const float* __restrict__ projw, const float* __restrict__ w1,
    const float* __restrict__ w2,
    __half* __restrict__ wt_iqkv, __half* __restrict__ wt_tqkv,
    __half* __restrict__ wt_proj, __half* __restrict__ wt_w1,
    __half* __restrict__ wt_w2)
{
    __shared__ float t[64][33];
    int b = blockIdx.x;
    const float* W; __half* WT; int K, N, nx, local;
    if (b < 1536)      { W = iqkvw; WT = wt_iqkv; K = 1024; N = 3072; nx = 96;  local = b; }
    else if (b < 3072) { W = tqkvw; WT = wt_tqkv; K = 1024; N = 3072; nx = 96;  local = b - 1536; }
    else if (b < 3584) { W = projw; WT = wt_proj; K = 1024; N = 1024; nx = 32;  local = b - 3072; }
    else if (b < 5632) { W = w1;    WT = wt_w1;   K = 1024; N = 4096; nx = 128; local = b - 3584; }
    else               { W = w2;    WT = wt_w2;   K = 4096; N = 1024; nx = 32;  local = b - 5632; }
    int n0 = (local % nx) * 32, k0 = (local / nx) * 64;
    int tid = threadIdx.x;
    int rr = tid >> 5, cc = tid & 31;
    #pragma unroll
    for (int i = 0; i < 8; i++)
        t[i * 8 + rr][cc] = W[(size_t)(k0 + i * 8 + rr) * N + n0 + cc];
    __syncthreads();
    int kk = cc * 2;
    #pragma unroll
    for (int i = 0; i < 4; i++) {
        int n = i * 8 + rr;
        __half2 hv = __floats2half2_rn(t[kk][n], t[kk + 1][n]);
        *(__half2*)(WT + (size_t)(n0 + n) * K + k0 + kk) = hv;
    }
}

// ---------------- modulation: silu(vec) @ mod_w + mod_b --------------------
__global__ void mod_kernel(const float* __restrict__ vec,
                           const float* __restrict__ imw, const float* __restrict__ imb,
                           const float* __restrict__ tmw, const float* __restrict__ tmb,
                           float* __restrict__ mod)
{
    __shared__ float sv[HID];
    int tid = threadIdx.x;
    for (int i = tid; i < HID; i += 128) {
        float x = vec[i];
        sv[i] = x / (1.f + expf(-x));
    }
    __syncthreads();
    int blk = blockIdx.x;
    bool is_img = blk < 48;
    int col = (is_img ? blk : blk - 48) * 128 + tid;
    const float* w = is_img ? imw : tmw;
    const float* b = is_img ? imb : tmb;
    float* out = mod + (is_img ? 0 : 6144);
    float a0 = 0.f, a1 = 0.f, a2 = 0.f, a3 = 0.f;
    for (int d = 0; d < HID; d += 4) {
        a0 += sv[d + 0] * w[(d + 0) * 6144 + col];
        a1 += sv[d + 1] * w[(d + 1) * 6144 + col];
        a2 += sv[d + 2] * w[(d + 2) * 6144 + col];
        a3 += sv[d + 3] * w[(d + 3) * 6144 + col];
    }
    out[col] = b[col] + ((a0 + a1) + (a2 + a3));
}

// ---------------- fused LayerNorm + modulate (fp16 output) -----------------
__device__ __forceinline__ void ln_mod_body(const float* __restrict__ xrow,
                                            const float* __restrict__ mod,
                                            int shift_off, int scale_off,
                                            __half* __restrict__ orow)
{
    __shared__ float red[2][8];
    int tid = threadIdx.x;
    float4 xv = ((const float4*)xrow)[tid];
    float s  = xv.x + xv.y + xv.z + xv.w;
    float s2 = xv.x * xv.x + xv.y * xv.y + xv.z * xv.z + xv.w * xv.w;
    #pragma unroll
    for (int o = 16; o; o >>= 1) {
        s  += __shfl_xor_sync(0xffffffffu, s,  o);
        s2 += __shfl_xor_sync(0xffffffffu, s2, o);
    }
    int warp = tid >> 5, lane = tid & 31;
    if (lane == 0) { red[0][warp] = s; red[1][warp] = s2; }
    __syncthreads();
    s = 0.f; s2 = 0.f;
    #pragma unroll
    for (int w = 0; w < 8; w++) { s += red[0][w]; s2 += red[1][w]; }
    float mean = s * (1.f / HID);
    float var  = s2 * (1.f / HID) - mean * mean;
    float rs = rsqrtf(var + 1e-6f);
    int c = tid * 4;
    float4 sc = *(const float4*)(mod + scale_off + c);
    float4 sh = *(const float4*)(mod + shift_off + c);
    *(__half2*)(orow + c)     = __floats2half2_rn((xv.x - mean) * rs * (1.f + sc.x) + sh.x,
                                                  (xv.y - mean) * rs * (1.f + sc.y) + sh.y);
    *(__half2*)(orow + c + 2) = __floats2half2_rn((xv.z - mean) * rs * (1.f + sc.z) + sh.z,
                                                  (xv.w - mean) * rs * (1.f + sc.w) + sh.w);
}

__global__ void ln_mod_kernel(const float* __restrict__ x,
                              const float* __restrict__ mod,
                              int shift_off, int scale_off,
                              __half* __restrict__ out)
{
    int row = blockIdx.x;
    ln_mod_body(x + (size_t)row * HID, mod, shift_off, scale_off,
                out + (size_t)row * HID);
}

__global__ void ln_mod2_kernel(const float* __restrict__ img,
                               const float* __restrict__ txt,
                               const float* __restrict__ mod,
                               __half* __restrict__ imgm,
                               __half* __restrict__ txtm)
{
    int row = blockIdx.x;
    if (row < LI)
        ln_mod_body(img + (size_t)row * HID, mod, 0, 1024,
                    imgm + (size_t)row * HID);
    else {
        int r = row - LI;
        ln_mod_body(txt + (size_t)r * HID, mod, 6144, 7168,
                    txtm + (size_t)r * HID);
    }
}

// ---------------- fp16 mma GEMM body: C[M,N] = A[M,K] @ BT[N,K]^T ----------
// CTA 128x128, BK=64, 3-stage cp.async pipeline, ONE sync per k-iteration.
// EPI: 0 = +bias (half); 1 = gelu(+bias) (half); 2 = res+gate (float);
//      3 = raw fp32 partial (no bias)
__device__ __forceinline__ float gelu_tanh(float x)
{
    return 0.5f * x * (1.f + tanhf(0.7978845608028654f * (x + 0.044715f * x * x * x)));
}

#define ROWH 144                       // bytes per padded smem row (64 halves + 16B)
#define TILEH (128 * ROWH)             // 18432 B per tile
#define MM_SMEM (6 * TILEH)            // 3 stages x (A,B) = 110592 B

__device__ __forceinline__ void mm_load_tile(uint32_t sbase, const __half* __restrict__ g,
                                             int ld, int k0)
{
    int tid = threadIdx.x;
    #pragma unroll
    for (int i = 0; i < 4; i++) {
        int id = tid + i * 256;
        int r = id >> 3, c = id & 7;
        uint32_t dst = sbase + r * ROWH + c * 16;
        const __half* src = g + (size_t)r * ld + k0 + c * 8;
        CP_ASYNC16(dst, src);
    }
}

template <int EPI, typename OT>
__device__ __forceinline__ void gemm_body(
    const __half* __restrict__ A, const __half* __restrict__ BT,
    const float* __restrict__ bias, const float* __restrict__ res,
    const float* __restrict__ gate, OT* __restrict__ C,
    int N, int K, int lda, int ldb, int row0, int col0, char* smem)
{
    uint32_t su = smem_u32(smem);
    uint32_t sA[3] = { su,             su + 2 * TILEH, su + 4 * TILEH };
    uint32_t sB[3] = { su + TILEH,     su + 3 * TILEH, su + 5 * TILEH };

    int tid = threadIdx.x;
    int wid = tid >> 5, lane = tid & 31;
    int warp_m = wid & 3, warp_n = wid >> 2;
    const __half* Ab = A + (size_t)row0 * lda;
    const __half* Bb = BT + (size_t)col0 * ldb;

    float acc[2][8][4];
    #pragma unroll
    for (int mt = 0; mt < 2; mt++)
        #pragma unroll
        for (int nt = 0; nt < 8; nt++)
            #pragma unroll
            for (int e = 0; e < 4; e++) acc[mt][nt][e] = 0.f;

    uint32_t aoff = (uint32_t)((warp_m * 32 + (lane & 15)) * ROWH + ((lane >> 4) & 1) * 16);
    uint32_t boff = (uint32_t)((warp_n * 64 + (lane & 15)) * ROWH + ((lane >> 4) & 1) * 16);

    int T = K >> 6;
    mm_load_tile(sA[0], Ab, lda, 0);
    mm_load_tile(sB[0], Bb, ldb, 0);
    CP_COMMIT();
    if (T > 1) {
        mm_load_tile(sA[1], Ab, lda, 64);
        mm_load_tile(sB[1], Bb, ldb, 64);
    }
    CP_COMMIT();

    int buf = 0;
    for (int t = 0; t < T; t++) {
        // stage t complete (at most one younger group may remain in flight)
        if (t + 1 < T) { CP_WAIT(1); } else { CP_WAIT(0); }
        __syncthreads();
        // issue stage t+2 into the buffer consumed at iteration t-1 (safe post-sync)
        if (t + 2 < T) {
            int nb = (buf + 2) % 3;
            mm_load_tile(sA[nb], Ab, lda, (t + 2) * 64);
            mm_load_tile(sB[nb], Bb, ldb, (t + 2) * 64);
            CP_COMMIT();
        }

        uint32_t Abase = sA[buf] + aoff;
        uint32_t Bbase = sB[buf] + boff;
        #pragma unroll
        for (int ks = 0; ks < 4; ks++) {
            uint32_t af[2][4], bf[4][4];
            LDSM_X4(af[0], Abase + ks * 32);
            LDSM_X4(af[1], Abase + 16 * ROWH + ks * 32);
            #pragma unroll
            for (int p = 0; p < 4; p++)
                LDSM_X4(bf[p], Bbase + p * 16 * ROWH + ks * 32);
            #pragma unroll
            for (int mt = 0; mt < 2; mt++)
                #pragma unroll
                for (int nt = 0; nt < 8; nt++) {
                    int p = nt >> 1, q = nt & 1;
                    MMA_F16(acc[mt][nt], af[mt], bf[p][q], bf[p][q + 2]);
                }
        }
        buf = (buf + 1) % 3;
    }

    int qr = lane >> 2, qc = (lane & 3) * 2;
    #pragma unroll
    for (int mt = 0; mt < 2; mt++) {
        int gr0 = row0 + warp_m * 32 + mt * 16 + qr;
        #pragma unroll
        for (int nt = 0; nt < 8; nt++) {
            int gc = col0 + warp_n * 64 + nt * 8 + qc;
            float2 bv = (EPI == 3) ? make_float2(0.f, 0.f)
                                   : *(const float2*)(bias + gc);
            #pragma unroll
            for (int h = 0; h < 2; h++) {
                int gr = gr0 + h * 8;
                float vx = acc[mt][nt][2 * h + 0] + bv.x;
                float vy = acc[mt][nt][2 * h + 1] + bv.y;
                if (EPI == 0) {
                    *(__half2*)((__half*)C + (size_t)gr * N + gc) =
                        __floats2half2_rn(vx, vy);
                } else if (EPI == 1) {
                    *(__half2*)((__half*)C + (size_t)gr * N + gc) =
                        __floats2half2_rn(gelu_tanh(vx), gelu_tanh(vy));
                } else if (EPI == 2) {
                    float2 rr = *(const float2*)(res + (size_t)gr * N + gc);
                    float2 gg = *(const float2*)(gate + gc);
                    float2 v = make_float2(rr.x + gg.x * vx, rr.y + gg.y * vy);
                    *(float2*)((float*)C + (size_t)gr * N + gc) = v;
                } else {
                    *(float2*)((float*)C + (size_t)gr * N + gc) =
                        make_float2(vx, vy);
                }
            }
        }
    }
}

template <int EPI, typename OT>
__global__ void __launch_bounds__(256) mma_gemm(
    const __half* __restrict__ A, const __half* __restrict__ BT,
    const float* __restrict__ bias, const float* __restrict__ res,
    const float* __restrict__ gate, OT* __restrict__ C,
    int N, int K)
{
    extern __shared__ char smem[];
    gemm_body<EPI, OT>(A, BT, bias, res, gate, C, N, K, K, K,
                       blockIdx.y * 128, blockIdx.x * 128, smem);
}

// merged QKV GEMM: blockIdx.y < 16 -> img rows, else txt rows
__global__ void __launch_bounds__(256) qkv_gemm(
    const __half* __restrict__ imgm, const __half* __restrict__ txtm,
    const __half* __restrict__ wt_i, const __half* __restrict__ wt_t,
    const float* __restrict__ bias_i, const float* __restrict__ bias_t,
    __half* __restrict__ qi, __half* __restrict__ qt)
{
    extern __shared__ char smem[];
    int by = blockIdx.y;
    if (by < 16)
        gemm_body<0, __half>(imgm, wt_i, bias_i, nullptr, nullptr, qi,
                             3 * HID, HID, HID, HID, by * 128, blockIdx.x * 128, smem);
    else
        gemm_body<0, __half>(txtm, wt_t, bias_t, nullptr, nullptr, qt,
                             3 * HID, HID, HID, HID, (by - 16) * 128, blockIdx.x * 128, smem);
}

// split-K x2 w2 GEMM: blockIdx.y < 16 -> K slice 0, else slice 1
__global__ void __launch_bounds__(256) w2_gemm(
    const __half* __restrict__ A, const __half* __restrict__ BT,
    float* __restrict__ part)
{
    extern __shared__ char smem[];
    int by = blockIdx.y;
    int slice = by >> 4;
    int row0 = (by & 15) * 128;
    gemm_body<3, float>(A + slice * 2048, BT + slice * 2048,
                        nullptr, nullptr, nullptr,
                        part + (size_t)slice * LI * HID,
                        HID, 2048, MLPD, MLPD, row0, blockIdx.x * 128, smem);
}

// combine: out = img2 + gate * (p0 + p1 + bias)
__global__ void w2_combine(const float* __restrict__ part,
                           const float* __restrict__ img2,
                           const float* __restrict__ bias,
                           const float* __restrict__ gate,
                           float* __restrict__ out)
{
    int row = blockIdx.x, tid = threadIdx.x;
    size_t base = (size_t)row * HID + tid * 4;
    float4 p0 = *(const float4*)(part + base);
    float4 p1 = *(const float4*)(part + (size_t)LI * HID + base);
    float4 rr = *(const float4*)(img2 + base);
    float4 bv = *(const float4*)(bias + tid * 4);
    float4 gg = *(const float4*)(gate + tid * 4);
    float4 o;
    o.x = rr.x + gg.x * (p0.x + p1.x + bv.x);
    o.y = rr.y + gg.y * (p0.y + p1.y + bv.y);
    o.z = rr.z + gg.z * (p0.z + p1.z + bv.z);
    o.w = rr.w + gg.w * (p0.w + p1.w + bv.w);
    *(float4*)(out + base) = o;
}

// ---------------- build q/k/v: rms-norm + rope + head layout (fp16) --------
__global__ void build_qkv_kernel(const __half* __restrict__ qkv_img,
                                 const __half* __restrict__ qkv_txt,
                                 const float* __restrict__ iqs, const float* __restrict__ iks,
                                 const float* __restrict__ tqs, const float* __restrict__ tks,
                                 const float* __restrict__ pe,
                                 __half* __restrict__ q, __half* __restrict__ k,
                                 __half* __restrict__ v)
{
    int s = blockIdx.x;
    int warp = threadIdx.x >> 5, lane = threadIdx.x & 31;
    bool is_txt = s < LT;
    const __half* src = is_txt ? (qkv_txt + (size_t)s * 3072)
                               : (qkv_img + (size_t)(s - LT) * 3072);
    for (int u = warp; u < 48; u += 8) {
        int which = u >> 4;       // 0=q 1=k 2=v
        int h = u & 15;
        const __half* base = src + which * HID + h * HD;
        float x0 = __half2float(base[2 * lane]);
        float x1 = __half2float(base[2 * lane + 1]);
        size_t didx = ((size_t)h * LTOT + s) * HD + 2 * lane;
        if (which == 2) {
            v[didx]     = __float2half_rn(x0);
            v[didx + 1] = __float2half_rn(x1);
        } else {
            float ss = x0 * x0 + x1 * x1;
            #pragma unroll
            for (int o = 16; o; o >>= 1) ss += __shfl_xor_sync(0xffffffffu, ss, o);
            float r = rsqrtf(ss * (1.f / HD) + 1e-6f);
            const float* sc = (which == 0) ? (is_txt ? tqs : iqs)
                                           : (is_txt ? tks : iks);
            x0 *= r * sc[2 * lane];
            x1 *= r * sc[2 * lane + 1];
            const float* p = pe + (size_t)s * 128 + lane * 4;
            float o0 = p[0] * x0 + p[1] * x1;
            float o1 = p[2] * x0 + p[3] * x1;
            if (which == 0) { o0 *= 0.125f; o1 *= 0.125f; }  // fold 1/sqrt(HD)
            __half* dst = (which == 0) ? q : k;
            dst[didx]     = __float2half_rn(o0);
            dst[didx + 1] = __float2half_rn(o1);
        }
    }
}

// ---------------- fp16 flash attention: BQ=128, BK=64, HD=64 ---------------
// 8 warps / 256 threads. cp.async double-buffered K/V; ONE sync per k-tile.
#define FROWH 72                 // halves per padded smem row (64 + 8)
#define FROWB 144                // bytes per padded smem row
#define FL_SMEM ((128 + 128 + 128 + 128) * FROWB)   // Q, K[2], V[2], P = 73728 B

__global__ void __launch_bounds__(256) flash_f16(
    const __half* __restrict__ Q, const __half* __restrict__ Kg,
    const __half* __restrict__ Vg, __half* __restrict__ O)
{
    extern __shared__ __half hsm[];
    __half* Qs = hsm;                        // [q][d] 128 rows
    uint32_t su = smem_u32(hsm);
    uint32_t uQ = su;
    uint32_t uK[2] = { su + 128 * FROWB, su + 192 * FROWB };
    uint32_t uV[2] = { su + 256 * FROWB, su + 320 * FROWB };
    uint32_t uP = su + 384 * FROWB;
    __half* Ps = hsm + 384 * FROWH;

    int tid = threadIdx.x;
    int wid = tid >> 5, lane = tid & 31;
    int h = blockIdx.y;
    int qb = LT + blockIdx.x * 128;
    const __half* Qh = Q + ((size_t)h * LTOT + qb) * HD;
    const __half* Kh = Kg + (size_t)h * LTOT * HD;
    const __half* Vh = Vg + (size_t)h * LTOT * HD;

    // load Q tile [128][64]
    #pragma unroll
    for (int i = 0; i < 4; i++) {
        int f = tid + i * 256;
        int r = f >> 3, c = (f & 7) * 8;
        *(float4*)&Qs[r * FROWH + c] = *(const float4*)(Qh + (size_t)r * HD + c);
    }

    // prologue: cp.async K/V tile 0 into buf 0
    {
        int r = tid >> 3, c = tid & 7;     // 32 rows per pass x 8 chunks? 256 thr -> r 0..31
        #pragma unroll
        for (int i = 0; i < 2; i++) {
            int id = tid + i * 256;
            int rr = id >> 3, cc = id & 7;
            CP_ASYNC16(uK[0] + rr * FROWB + cc * 16, Kh + (size_t)rr * HD + cc * 8);
            CP_ASYNC16(uV[0] + rr * FROWB + cc * 16, Vh + (size_t)rr * HD + cc * 8);
        }
        (void)r; (void)c;
        CP_COMMIT();
    }

    uint32_t aoff = (uint32_t)((wid * 16 + (lane & 15)) * FROWB + ((lane >> 4) & 1) * 16);
    uint32_t boff = (uint32_t)((lane & 15) * FROWB + ((lane >> 4) & 1) * 16);
    uint32_t voff = (uint32_t)(((lane & 7) + ((lane >> 3) & 1) * 8) * FROWB
                               + ((lane >> 4) & 1) * 16);

    float m0 = -1e30f, m1 = -1e30f, ls0 = 0.f, ls1 = 0.f;
    float oacc[8][4];
    #pragma unroll
    for (int nt = 0; nt < 8; nt++)
        #pragma unroll
        for (int e = 0; e < 4; e++) oacc[nt][e] = 0.f;

    int prow0 = wid * 16 + (lane >> 2);
    int pcol  = 2 * (lane & 3);

    int buf = 0;
    for (int kb = 0; kb < LTOT; kb += 64) {
        CP_WAIT(0);
        __syncthreads();
        // issue next K/V tile into the other buffer (overlaps with compute)
        if (kb + 64 < LTOT) {
            int nb = buf ^ 1;
            #pragma unroll
            for (int i = 0; i < 2; i++) {
                int id = tid + i * 256;
                int rr = id >> 3, cc = id & 7;
                CP_ASYNC16(uK[nb] + rr * FROWB + cc * 16,
                           Kh + (size_t)(kb + 64 + rr) * HD + cc * 8);
                CP_ASYNC16(uV[nb] + rr * FROWB + cc * 16,
                           Vh + (size_t)(kb + 64 + rr) * HD + cc * 8);
            }
            CP_COMMIT();
        }

        // S = Q @ K^T  (per warp: 16 x 64)
        float sacc[8][4];
        #pragma unroll
        for (int nt = 0; nt < 8; nt++)
            #pragma unroll
            for (int e = 0; e < 4; e++) sacc[nt][e] = 0.f;
        #pragma unroll
        for (int ks = 0; ks < 4; ks++) {
            uint32_t af[4], bf[4][4];
            LDSM_X4(af, uQ + aoff + ks * 32);
            #pragma unroll
            for (int p = 0; p < 4; p++)
                LDSM_X4(bf[p], uK[buf] + boff + p * 16 * FROWB + ks * 32);
            #pragma unroll
            for (int nt = 0; nt < 8; nt++) {
                int p = nt >> 1, q = nt & 1;
                MMA_F16(sacc[nt], af, bf[p][q], bf[p][q + 2]);
            }
        }

        // online softmax (rows prow0, prow0+8)
        float mx0 = -1e30f, mx1 = -1e30f;
        #pragma unroll
        for (int nt = 0; nt < 8; nt++) {
            mx0 = fmaxf(mx0, fmaxf(sacc[nt][0], sacc[nt][1]));
            mx1 = fmaxf(mx1, fmaxf(sacc[nt][2], sacc[nt][3]));
        }
        mx0 = fmaxf(mx0, __shfl_xor_sync(0xffffffffu, mx0, 1));
        mx0 = fmaxf(mx0, __shfl_xor_sync(0xffffffffu, mx0, 2));
        mx1 = fmaxf(mx1, __shfl_xor_sync(0xffffffffu, mx1, 1));
        mx1 = fmaxf(mx1, __shfl_xor_sync(0xffffffffu, mx1, 2));
        float mn0 = fmaxf(m0, mx0), mn1 = fmaxf(m1, mx1);
        float c0 = __expf(m0 - mn0), c1 = __expf(m1 - mn1);
        float ps0 = 0.f, ps1 = 0.f;
        #pragma unroll
        for (int nt = 0; nt < 8; nt++) {
            float p00 = __expf(sacc[nt][0] - mn0);
            float p01 = __expf(sacc[nt][1] - mn0);
            float p10 = __expf(sacc[nt][2] - mn1);
            float p11 = __expf(sacc[nt][3] - mn1);
            ps0 += p00 + p01; ps1 += p10 + p11;
            int col = nt * 8 + pcol;
            *(__half2*)&Ps[prow0 * FROWH + col] = __floats2half2_rn(p00, p01);
            *(__half2*)&Ps[(prow0 + 8) * FROWH + col] = __floats2half2_rn(p10, p11);
        }
        ps0 += __shfl_xor_sync(0xffffffffu, ps0, 1);
        ps0 += __shfl_xor_sync(0xffffffffu, ps0, 2);
        ps1 += __shfl_xor_sync(0xffffffffu, ps1, 1);
        ps1 += __shfl_xor_sync(0xffffffffu, ps1, 2);
        ls0 = ls0 * c0 + ps0;
        ls1 = ls1 * c1 + ps1;
        m0 = mn0; m1 = mn1;
        #pragma unroll
        for (int nt = 0; nt < 8; nt++) {
            oacc[nt][0] *= c0; oacc[nt][1] *= c0;
            oacc[nt][2] *= c1; oacc[nt][3] *= c1;
        }
        __syncwarp();

        // O += P @ V  (Ps rows are warp-private; V via ldmatrix.trans)
        #pragma unroll
        for (int ks = 0; ks < 4; ks++) {
            uint32_t af[4], bf[4][4];
            LDSM_X4(af, uP + aoff + ks * 32);
            #pragma unroll
            for (int p = 0; p < 4; p++)
                LDSM_X4_T(bf[p], uV[buf] + voff + ks * 16 * FROWB + p * 32);
            #pragma unroll
            for (int nt = 0; nt < 8; nt++) {
                int p = nt >> 1, q = nt & 1;
                MMA_F16(oacc[nt], af, bf[p][2 * q], bf[p][2 * q + 1]);
            }
        }
        buf ^= 1;
    }

    float inv0 = 1.f / ls0, inv1 = 1.f / ls1;
    int r0 = qb + prow0, r1 = r0 + 8;
    #pragma unroll
    for (int nt = 0; nt < 8; nt++) {
        int col = h * HD + nt * 8 + pcol;
        *(__half2*)(O + (size_t)r0 * HID + col) =
            __floats2half2_rn(oacc[nt][0] * inv0, oacc[nt][1] * inv0);
        *(__half2*)(O + (size_t)r1 * HID + col) =
            __floats2half2_rn(oacc[nt][2] * inv1, oacc[nt][3] * inv1);
    }
}

// ---------------- launch ---------------------------------------------------
extern "C" void kernel_launch(void* const* d_in, const int* in_sizes, int n_in,
                              void* d_out, int out_size)
{
    const float* img   = (const float*)d_in[0];
    const float* txt   = (const float*)d_in[1];
    const float* pe    = (const float*)d_in[2];
    const float* vec   = (const float*)d_in[3];
    const float* imw   = (const float*)d_in[4];
    const float* imb   = (const float*)d_in[5];
    const float* tmw   = (const float*)d_in[6];
    const float* tmb   = (const float*)d_in[7];
    const float* iqkvw = (const float*)d_in[8];
    const float* iqkvb = (const float*)d_in[9];
    const float* iqs   = (const float*)d_in[10];
    const float* iks   = (const float*)d_in[11];
    const float* projw = (const float*)d_in[12];
    const float* projb = (const float*)d_in[13];
    const float* tqkvw = (const float*)d_in[14];
    const float* tqkvb = (const float*)d_in[15];
    const float* tqs   = (const float*)d_in[16];
    const float* tks   = (const float*)d_in[17];
    const float* w1    = (const float*)d_in[18];
    const float* b1    = (const float*)d_in[19];
    const float* w2    = (const float*)d_in[20];
    const float* b2    = (const float*)d_in[21];

    float *mod, *img2, *w2part;
    __half *imgm, *txtm, *qi, *qt, *q, *k, *v, *attn, *ln2, *mlp;
    __half *wt_iqkv, *wt_tqkv, *wt_proj, *wt_w1, *wt_w2;
    cudaGetSymbolAddress((void**)&mod,  g_mod);
    cudaGetSymbolAddress((void**)&imgm, g_imgm);
    cudaGetSymbolAddress((void**)&txtm, g_txtm);
    cudaGetSymbolAddress((void**)&qi,   g_qkv_img);
    cudaGetSymbolAddress((void**)&qt,   g_qkv_txt);
    cudaGetSymbolAddress((void**)&q,    g_q);
    cudaGetSymbolAddress((void**)&k,    g_k);
    cudaGetSymbolAddress((void**)&v,    g_v);
    cudaGetSymbolAddress((void**)&attn, g_attn);
    cudaGetSymbolAddress((void**)&img2, g_img2);
    cudaGetSymbolAddress((void**)&ln2,  g_ln2);
    cudaGetSymbolAddress((void**)&mlp,  g_mlp);
    cudaGetSymbolAddress((void**)&w2part, g_w2part);
    cudaGetSymbolAddress((void**)&wt_iqkv, g_wt_iqkv);
    cudaGetSymbolAddress((void**)&wt_tqkv, g_wt_tqkv);
    cudaGetSymbolAddress((void**)&wt_proj, g_wt_proj);
    cudaGetSymbolAddress((void**)&wt_w1,   g_wt_w1);
    cudaGetSymbolAddress((void**)&wt_w2,   g_wt_w2);

    cudaFuncSetAttribute(flash_f16, cudaFuncAttributeMaxDynamicSharedMemorySize, FL_SMEM);
    cudaFuncSetAttribute(qkv_gemm,            cudaFuncAttributeMaxDynamicSharedMemorySize, MM_SMEM);
    cudaFuncSetAttribute(w2_gemm,             cudaFuncAttributeMaxDynamicSharedMemorySize, MM_SMEM);
    cudaFuncSetAttribute(mma_gemm<1, __half>, cudaFuncAttributeMaxDynamicSharedMemorySize, MM_SMEM);
    cudaFuncSetAttribute(mma_gemm<2, float>,  cudaFuncAttributeMaxDynamicSharedMemorySize, MM_SMEM);

    // 0) weight transposes -> fp16 [N,K] (single launch)
    transpose_all<<<7680, 256>>>(iqkvw, tqkvw, projw, w1, w2,
                                 wt_iqkv, wt_tqkv, wt_proj, wt_w1, wt_w2);
    // 1) modulation vectors
    mod_kernel<<<96, 128>>>(vec, imw, imb, tmw, tmb, mod);
    // 2) LN + modulate (img + txt, one launch)
    ln_mod2_kernel<<<LI + LT, 256>>>(img, txt, mod, imgm, txtm);
    // 3) QKV GEMMs (img + txt merged in one launch)
    { dim3 g(24, 18); qkv_gemm<<<g, 256, MM_SMEM>>>(imgm, txtm, wt_iqkv, wt_tqkv,
                                                    iqkvb, tqkvb, qi, qt); }
    // 4) rms-norm + rope + head layout (fp16)
    build_qkv_kernel<<<LTOT, 256>>>(qi, qt, iqs, iks, tqs, tks, pe, q, k, v);
    // 5) attention (fp16 flash, img queries only, BQ=128)
    { dim3 g(LI / 128, NHEAD);
      flash_f16<<<g, 256, FL_SMEM>>>(q, k, v, attn); }
    // 6) proj + gated residual (img rows only) -> fp32
    { dim3 g(8, 16); mma_gemm<2, float><<<g, 256, MM_SMEM>>>(attn + (size_t)LT * HID, wt_proj, projb,
                                                             img, mod + 2048, img2, HID, HID); }
    // 7) LN2 + modulate -> fp16
    ln_mod_kernel<<<LI, 256>>>(img2, mod, 3072, 4096, ln2);
    // 8) MLP: w1 gemm, then split-K2 w2 + combine
    { dim3 g(32, 16); mma_gemm<1, __half><<<g, 256, MM_SMEM>>>(ln2, wt_w1, b1, nullptr, nullptr, mlp, MLPD, HID); }
    { dim3 g(8, 32);  w2_gemm<<<g, 256, MM_SMEM>>>(mlp, wt_w2, w2part); }
    w2_combine<<<LI, 256>>>(w2part, img2, b2, mod + 5120, (float*)d_out);
}

// round 14
// speedup vs baseline: 1.0226x; 1.0226x over previous
#include <cuda_runtime.h>
#include <cuda_fp16.h>
#include <cstdint>
#include <math.h>

// Problem constants
#define HID   1024
#define LT    256
#define LI    2048
#define LTOT  2304
#define NHEAD 16
#define HD    64
#define MLPD  4096

// ---------------- scratch (device globals; no cudaMalloc allowed) ----------
__device__ float  g_mod[12288];
__device__ __half g_imgm[LI * HID];
__device__ __half g_txtm[LT * HID];
__device__ __half g_qkv_img[LI * 3 * HID];
__device__ __half g_qkv_txt[LT * 3 * HID];
__device__ __half g_q[NHEAD * LTOT * HD];
__device__ __half g_k[NHEAD * LTOT * HD];
__device__ __half g_v[NHEAD * LTOT * HD];
__device__ __half g_attn[LTOT * HID];
__device__ float  g_img2[LI * HID];
__device__ __half g_ln2[LI * HID];
__device__ __half g_mlp[LI * MLPD];
__device__ float  g_w2part[2 * LI * HID];
// transposed weights [N,K] (fp16)
__device__ __half g_wt_iqkv[3 * HID * HID];
__device__ __half g_wt_tqkv[3 * HID * HID];
__device__ __half g_wt_proj[HID * HID];
__device__ __half g_wt_w1[MLPD * HID];
__device__ __half g_wt_w2[HID * MLPD];

// ---------------- PTX helpers ----------------------------------------------
__device__ __forceinline__ uint32_t smem_u32(const void* p) {
    uint32_t a;
    asm("{ .reg .u64 t; cvta.to.shared.u64 t, %1; cvt.u32.u64 %0, t; }" : "=r"(a) : "l"(p));
    return a;
}
__device__ __forceinline__ uint32_t pack_h2(float a, float b) {
    __half2 h = __floats2half2_rn(a, b);
    return *(uint32_t*)&h;
}
#define CP_ASYNC16(dst, src) \
    asm volatile("cp.async.cg.shared.global [%0], [%1], 16;" :: "r"(dst), "l"(src))
#define CP_COMMIT() asm volatile("cp.async.commit_group;")
#define CP_WAIT(n)  asm volatile("cp.async.wait_group %0;" :: "n"(n))

#define LDSM_X4(r, a)                                                          \
    asm volatile("ldmatrix.sync.aligned.m8n8.x4.shared.b16 {%0,%1,%2,%3}, [%4];" \
        : "=r"((r)[0]), "=r"((r)[1]), "=r"((r)[2]), "=r"((r)[3]) : "r"(a))

#define LDSM_X4_T(r, a)                                                        \
    asm volatile("ldmatrix.sync.aligned.m8n8.x4.trans.shared.b16 {%0,%1,%2,%3}, [%4];" \
        : "=r"((r)[0]), "=r"((r)[1]), "=r"((r)[2]), "=r"((r)[3]) : "r"(a))

// D += A(f16) * B(f16), fp32 accumulate, m16n8k16
#define MMA_F16(d, a, b0, b1)                                                  \
    asm volatile("mma.sync.aligned.m16n8k16.row.col.f32.f16.f16.f32 "          \
        "{%0,%1,%2,%3}, {%4,%5,%6,%7}, {%8,%9}, {%0,%1,%2,%3};"                \
        : "+f"((d)[0]), "+f"((d)[1]), "+f"((d)[2]), "+f"((d)[3])               \
        : "r"((a)[0]), "r"((a)[1]), "r"((a)[2]), "r"((a)[3]),                  \
          "r"(b0), "r"(b1))

// ---------------- merged weight transpose + f16: W[K,N] -> WT[N,K] ---------
__global__ void transpose_all(
    const float* __restrict__ iqkvw, const float* __restrict__ tqkvw,
    const float* __restrict__ projw, const float* __restrict__ w1,
    const float* __restrict__ w2,
    __half* __restrict__ wt_iqkv, __half* __restrict__ wt_tqkv,
    __half* __restrict__ wt_proj, __half* __restrict__ wt_w1,
    __half* __restrict__ wt_w2)
{
    __shared__ float t[64][33];
    int b = blockIdx.x;
    const float* W; __half* WT; int K, N, nx, local;
    if (b < 1536)      { W = iqkvw; WT = wt_iqkv; K = 1024; N = 3072; nx = 96;  local = b; }
    else if (b < 3072) { W = tqkvw; WT = wt_tqkv; K = 1024; N = 3072; nx = 96;  local = b - 1536; }
    else if (b < 3584) { W = projw; WT = wt_proj; K = 1024; N = 1024; nx = 32;  local = b - 3072; }
    else if (b < 5632) { W = w1;    WT = wt_w1;   K = 1024; N = 4096; nx = 128; local = b - 3584; }
    else               { W = w2;    WT = wt_w2;   K = 4096; N = 1024; nx = 32;  local = b - 5632; }
    int n0 = (local % nx) * 32, k0 = (local / nx) * 64;
    int tid = threadIdx.x;
    int rr = tid >> 5, cc = tid & 31;
    #pragma unroll
    for (int i = 0; i < 8; i++)
        t[i * 8 + rr][cc] = W[(size_t)(k0 + i * 8 + rr) * N + n0 + cc];
    __syncthreads();
    int kk = cc * 2;
    #pragma unroll
    for (int i = 0; i < 4; i++) {
        int n = i * 8 + rr;
        __half2 hv = __floats2half2_rn(t[kk][n], t[kk + 1][n]);
        *(__half2*)(WT + (size_t)(n0 + n) * K + k0 + kk) = hv;
    }
}

// ---------------- modulation: silu(vec) @ mod_w + mod_b --------------------
__global__ void mod_kernel(const float* __restrict__ vec,
                           const float* __restrict__ imw, const float* __restrict__ imb,
                           const float* __restrict__ tmw, const float* __restrict__ tmb,
                           float* __restrict__ mod)
{
    __shared__ float sv[HID];
    int tid = threadIdx.x;
    for (int i = tid; i < HID; i += 128) {
        float x = vec[i];
        sv[i] = x / (1.f + expf(-x));
    }
    __syncthreads();
    int blk = blockIdx.x;
    bool is_img = blk < 48;
    int col = (is_img ? blk : blk - 48) * 128 + tid;
    const float* w = is_img ? imw : tmw;
    const float* b = is_img ? imb : tmb;
    float* out = mod + (is_img ? 0 : 6144);
    float a0 = 0.f, a1 = 0.f, a2 = 0.f, a3 = 0.f;
    for (int d = 0; d < HID; d += 4) {
        a0 += sv[d + 0] * w[(d + 0) * 6144 + col];
        a1 += sv[d + 1] * w[(d + 1) * 6144 + col];
        a2 += sv[d + 2] * w[(d + 2) * 6144 + col];
        a3 += sv[d + 3] * w[(d + 3) * 6144 + col];
    }
    out[col] = b[col] + ((a0 + a1) + (a2 + a3));
}

// ---------------- fused LayerNorm + modulate (fp16 output) -----------------
__device__ __forceinline__ void ln_mod_body(const float* __restrict__ xrow,
                                            const float* __restrict__ mod,
                                            int shift_off, int scale_off,
                                            __half* __restrict__ orow)
{
    __shared__ float red[2][8];
    int tid = threadIdx.x;
    float4 xv = ((const float4*)xrow)[tid];
    float s  = xv.x + xv.y + xv.z + xv.w;
    float s2 = xv.x * xv.x + xv.y * xv.y + xv.z * xv.z + xv.w * xv.w;
    #pragma unroll
    for (int o = 16; o; o >>= 1) {
        s  += __shfl_xor_sync(0xffffffffu, s,  o);
        s2 += __shfl_xor_sync(0xffffffffu, s2, o);
    }
    int warp = tid >> 5, lane = tid & 31;
    if (lane == 0) { red[0][warp] = s; red[1][warp] = s2; }
    __syncthreads();
    s = 0.f; s2 = 0.f;
    #pragma unroll
    for (int w = 0; w < 8; w++) { s += red[0][w]; s2 += red[1][w]; }
    float mean = s * (1.f / HID);
    float var  = s2 * (1.f / HID) - mean * mean;
    float rs = rsqrtf(var + 1e-6f);
    int c = tid * 4;
    float4 sc = *(const float4*)(mod + scale_off + c);
    float4 sh = *(const float4*)(mod + shift_off + c);
    *(__half2*)(orow + c)     = __floats2half2_rn((xv.x - mean) * rs * (1.f + sc.x) + sh.x,
                                                  (xv.y - mean) * rs * (1.f + sc.y) + sh.y);
    *(__half2*)(orow + c + 2) = __floats2half2_rn((xv.z - mean) * rs * (1.f + sc.z) + sh.z,
                                                  (xv.w - mean) * rs * (1.f + sc.w) + sh.w);
}

__global__ void ln_mod_kernel(const float* __restrict__ x,
                              const float* __restrict__ mod,
                              int shift_off, int scale_off,
                              __half* __restrict__ out)
{
    int row = blockIdx.x;
    ln_mod_body(x + (size_t)row * HID, mod, shift_off, scale_off,
                out + (size_t)row * HID);
}

__global__ void ln_mod2_kernel(const float* __restrict__ img,
                               const float* __restrict__ txt,
                               const float* __restrict__ mod,
                               __half* __restrict__ imgm,
                               __half* __restrict__ txtm)
{
    int row = blockIdx.x;
    if (row < LI)
        ln_mod_body(img + (size_t)row * HID, mod, 0, 1024,
                    imgm + (size_t)row * HID);
    else {
        int r = row - LI;
        ln_mod_body(txt + (size_t)r * HID, mod, 6144, 7168,
                    txtm + (size_t)r * HID);
    }
}

// ---------------- fp16 mma GEMM body: C[M,N] = A[M,K] @ BT[N,K]^T ----------
__device__ __forceinline__ float gelu_tanh(float x)
{
    return 0.5f * x * (1.f + tanhf(0.7978845608028654f * (x + 0.044715f * x * x * x)));
}

#define ROWH 144                       // bytes per padded smem row (64 halves + 16B)
#define TILEH (128 * ROWH)             // 18432 B per tile
#define MM_SMEM (6 * TILEH)            // 3 stages x (A,B) = 110592 B

__device__ __forceinline__ void mm_load_tile(uint32_t sbase, const __half* __restrict__ g,
                                             int ld, int k0)
{
    int tid = threadIdx.x;
    #pragma unroll
    for (int i = 0; i < 4; i++) {
        int id = tid + i * 256;
        int r = id >> 3, c = id & 7;
        uint32_t dst = sbase + r * ROWH + c * 16;
        const __half* src = g + (size_t)r * ld + k0 + c * 8;
        CP_ASYNC16(dst, src);
    }
}

template <int EPI, typename OT>
__device__ __forceinline__ void gemm_body(
    const __half* __restrict__ A, const __half* __restrict__ BT,
    const float* __restrict__ bias, const float* __restrict__ res,
    const float* __restrict__ gate, OT* __restrict__ C,
    int N, int K, int lda, int ldb, int row0, int col0, char* smem)
{
    uint32_t su = smem_u32(smem);
    uint32_t sA[3] = { su,             su + 2 * TILEH, su + 4 * TILEH };
    uint32_t sB[3] = { su + TILEH,     su + 3 * TILEH, su + 5 * TILEH };

    int tid = threadIdx.x;
    int wid = tid >> 5, lane = tid & 31;
    int warp_m = wid & 3, warp_n = wid >> 2;
    const __half* Ab = A + (size_t)row0 * lda;
    const __half* Bb = BT + (size_t)col0 * ldb;

    float acc[2][8][4];
    #pragma unroll
    for (int mt = 0; mt < 2; mt++)
        #pragma unroll
        for (int nt = 0; nt < 8; nt++)
            #pragma unroll
            for (int e = 0; e < 4; e++) acc[mt][nt][e] = 0.f;

    uint32_t aoff = (uint32_t)((warp_m * 32 + (lane & 15)) * ROWH + ((lane >> 4) & 1) * 16);
    uint32_t boff = (uint32_t)((warp_n * 64 + (lane & 15)) * ROWH + ((lane >> 4) & 1) * 16);

    int T = K >> 6;
    mm_load_tile(sA[0], Ab, lda, 0);
    mm_load_tile(sB[0], Bb, ldb, 0);
    CP_COMMIT();
    if (T > 1) {
        mm_load_tile(sA[1], Ab, lda, 64);
        mm_load_tile(sB[1], Bb, ldb, 64);
    }
    CP_COMMIT();

    int buf = 0;
    for (int t = 0; t < T; t++) {
        if (t + 1 < T) { CP_WAIT(1); } else { CP_WAIT(0); }
        __syncthreads();
        if (t + 2 < T) {
            int nb = (buf + 2) % 3;
            mm_load_tile(sA[nb], Ab, lda, (t + 2) * 64);
            mm_load_tile(sB[nb], Bb, ldb, (t + 2) * 64);
            CP_COMMIT();
        }

        uint32_t Abase = sA[buf] + aoff;
        uint32_t Bbase = sB[buf] + boff;
        #pragma unroll
        for (int ks = 0; ks < 4; ks++) {
            uint32_t af[2][4], bf[4][4];
            LDSM_X4(af[0], Abase + ks * 32);
            LDSM_X4(af[1], Abase + 16 * ROWH + ks * 32);
            #pragma unroll
            for (int p = 0; p < 4; p++)
                LDSM_X4(bf[p], Bbase + p * 16 * ROWH + ks * 32);
            #pragma unroll
            for (int mt = 0; mt < 2; mt++)
                #pragma unroll
                for (int nt = 0; nt < 8; nt++) {
                    int p = nt >> 1, q = nt & 1;
                    MMA_F16(acc[mt][nt], af[mt], bf[p][q], bf[p][q + 2]);
                }
        }
        buf = (buf + 1) % 3;
    }

    int qr = lane >> 2, qc = (lane & 3) * 2;
    #pragma unroll
    for (int mt = 0; mt < 2; mt++) {
        int gr0 = row0 + warp_m * 32 + mt * 16 + qr;
        #pragma unroll
        for (int nt = 0; nt < 8; nt++) {
            int gc = col0 + warp_n * 64 + nt * 8 + qc;
            float2 bv = (EPI == 3) ? make_float2(0.f, 0.f)
                                   : *(const float2*)(bias + gc);
            #pragma unroll
            for (int h = 0; h < 2; h++) {
                int gr = gr0 + h * 8;
                float vx = acc[mt][nt][2 * h + 0] + bv.x;
                float vy = acc[mt][nt][2 * h + 1] + bv.y;
                if (EPI == 0) {
                    *(__half2*)((__half*)C + (size_t)gr * N + gc) =
                        __floats2half2_rn(vx, vy);
                } else if (EPI == 1) {
                    *(__half2*)((__half*)C + (size_t)gr * N + gc) =
                        __floats2half2_rn(gelu_tanh(vx), gelu_tanh(vy));
                } else if (EPI == 2) {
                    float2 rr = *(const float2*)(res + (size_t)gr * N + gc);
                    float2 gg = *(const float2*)(gate + gc);
                    float2 v = make_float2(rr.x + gg.x * vx, rr.y + gg.y * vy);
                    *(float2*)((float*)C + (size_t)gr * N + gc) = v;
                } else {
                    *(float2*)((float*)C + (size_t)gr * N + gc) =
                        make_float2(vx, vy);
                }
            }
        }
    }
}

template <int EPI, typename OT>
__global__ void __launch_bounds__(256) mma_gemm(
    const __half* __restrict__ A, const __half* __restrict__ BT,
    const float* __restrict__ bias, const float* __restrict__ res,
    const float* __restrict__ gate, OT* __restrict__ C,
    int N, int K)
{
    extern __shared__ char smem[];
    gemm_body<EPI, OT>(A, BT, bias, res, gate, C, N, K, K, K,
                       blockIdx.y * 128, blockIdx.x * 128, smem);
}

// merged QKV GEMM: blockIdx.y < 16 -> img rows, else txt rows
__global__ void __launch_bounds__(256) qkv_gemm(
    const __half* __restrict__ imgm, const __half* __restrict__ txtm,
    const __half* __restrict__ wt_i, const __half* __restrict__ wt_t,
    const float* __restrict__ bias_i, const float* __restrict__ bias_t,
    __half* __restrict__ qi, __half* __restrict__ qt)
{
    extern __shared__ char smem[];
    int by = blockIdx.y;
    if (by < 16)
        gemm_body<0, __half>(imgm, wt_i, bias_i, nullptr, nullptr, qi,
                             3 * HID, HID, HID, HID, by * 128, blockIdx.x * 128, smem);
    else
        gemm_body<0, __half>(txtm, wt_t, bias_t, nullptr, nullptr, qt,
                             3 * HID, HID, HID, HID, (by - 16) * 128, blockIdx.x * 128, smem);
}

// split-K x2 w2 GEMM: blockIdx.y < 16 -> K slice 0, else slice 1
__global__ void __launch_bounds__(256) w2_gemm(
    const __half* __restrict__ A, const __half* __restrict__ BT,
    float* __restrict__ part)
{
    extern __shared__ char smem[];
    int by = blockIdx.y;
    int slice = by >> 4;
    int row0 = (by & 15) * 128;
    gemm_body<3, float>(A + slice * 2048, BT + slice * 2048,
                        nullptr, nullptr, nullptr,
                        part + (size_t)slice * LI * HID,
                        HID, 2048, MLPD, MLPD, row0, blockIdx.x * 128, smem);
}

// combine: out = img2 + gate * (p0 + p1 + bias)
__global__ void w2_combine(const float* __restrict__ part,
                           const float* __restrict__ img2,
                           const float* __restrict__ bias,
                           const float* __restrict__ gate,
                           float* __restrict__ out)
{
    int row = blockIdx.x, tid = threadIdx.x;
    size_t base = (size_t)row * HID + tid * 4;
    float4 p0 = *(const float4*)(part + base);
    float4 p1 = *(const float4*)(part + (size_t)LI * HID + base);
    float4 rr = *(const float4*)(img2 + base);
    float4 bv = *(const float4*)(bias + tid * 4);
    float4 gg = *(const float4*)(gate + tid * 4);
    float4 o;
    o.x = rr.x + gg.x * (p0.x + p1.x + bv.x);
    o.y = rr.y + gg.y * (p0.y + p1.y + bv.y);
    o.z = rr.z + gg.z * (p0.z + p1.z + bv.z);
    o.w = rr.w + gg.w * (p0.w + p1.w + bv.w);
    *(float4*)(out + base) = o;
}

// ---------------- build q/k/v: rms-norm + rope + head layout (fp16) --------
__global__ void build_qkv_kernel(const __half* __restrict__ qkv_img,
                                 const __half* __restrict__ qkv_txt,
                                 const float* __restrict__ iqs, const float* __restrict__ iks,
                                 const float* __restrict__ tqs, const float* __restrict__ tks,
                                 const float* __restrict__ pe,
                                 __half* __restrict__ q, __half* __restrict__ k,
                                 __half* __restrict__ v)
{
    int s = blockIdx.x;
    int warp = threadIdx.x >> 5, lane = threadIdx.x & 31;
    bool is_txt = s < LT;
    const __half* src = is_txt ? (qkv_txt + (size_t)s * 3072)
                               : (qkv_img + (size_t)(s - LT) * 3072);
    for (int u = warp; u < 48; u += 8) {
        int which = u >> 4;       // 0=q 1=k 2=v
        int h = u & 15;
        const __half* base = src + which * HID + h * HD;
        float x0 = __half2float(base[2 * lane]);
        float x1 = __half2float(base[2 * lane + 1]);
        size_t didx = ((size_t)h * LTOT + s) * HD + 2 * lane;
        if (which == 2) {
            v[didx]     = __float2half_rn(x0);
            v[didx + 1] = __float2half_rn(x1);
        } else {
            float ss = x0 * x0 + x1 * x1;
            #pragma unroll
            for (int o = 16; o; o >>= 1) ss += __shfl_xor_sync(0xffffffffu, ss, o);
            float r = rsqrtf(ss * (1.f / HD) + 1e-6f);
            const float* sc = (which == 0) ? (is_txt ? tqs : iqs)
                                           : (is_txt ? tks : iks);
            x0 *= r * sc[2 * lane];
            x1 *= r * sc[2 * lane + 1];
            const float* p = pe + (size_t)s * 128 + lane * 4;
            float o0 = p[0] * x0 + p[1] * x1;
            float o1 = p[2] * x0 + p[3] * x1;
            if (which == 0) { o0 *= 0.125f; o1 *= 0.125f; }  // fold 1/sqrt(HD)
            __half* dst = (which == 0) ? q : k;
            dst[didx]     = __float2half_rn(o0);
            dst[didx + 1] = __float2half_rn(o1);
        }
    }
}

// ---------------- fp16 flash attention: BQ=128, BK=64, HD=64 ---------------
// 8 warps / 256 threads. cp.async double-buffered K/V. Static-max softmax
// (|logit| <= 8 by Cauchy-Schwarz after RMS norm + orthogonal RoPE), and P
// repacked register-to-register into mma A-fragments (no smem round trip).
#define FROWH 72                 // halves per padded smem row (64 + 8)
#define FROWB 144                // bytes per padded smem row
#define FL_SMEM ((128 + 128 + 128) * FROWB)   // Q, K[2], V[2] = 55296 B

__global__ void __launch_bounds__(256) flash_f16(
    const __half* __restrict__ Q, const __half* __restrict__ Kg,
    const __half* __restrict__ Vg, __half* __restrict__ O)
{
    extern __shared__ __half hsm[];
    __half* Qs = hsm;                        // [q][d] 128 rows
    uint32_t su = smem_u32(hsm);
    uint32_t uQ = su;
    uint32_t uK[2] = { su + 128 * FROWB, su + 192 * FROWB };
    uint32_t uV[2] = { su + 256 * FROWB, su + 320 * FROWB };

    int tid = threadIdx.x;
    int wid = tid >> 5, lane = tid & 31;
    int h = blockIdx.y;
    int qb = LT + blockIdx.x * 128;
    const __half* Qh = Q + ((size_t)h * LTOT + qb) * HD;
    const __half* Kh = Kg + (size_t)h * LTOT * HD;
    const __half* Vh = Vg + (size_t)h * LTOT * HD;

    // load Q tile [128][64]
    #pragma unroll
    for (int i = 0; i < 4; i++) {
        int f = tid + i * 256;
        int r = f >> 3, c = (f & 7) * 8;
        *(float4*)&Qs[r * FROWH + c] = *(const float4*)(Qh + (size_t)r * HD + c);
    }

    // prologue: cp.async K/V tile 0 into buf 0
    #pragma unroll
    for (int i = 0; i < 2; i++) {
        int id = tid + i * 256;
        int rr = id >> 3, cc = id & 7;
        CP_ASYNC16(uK[0] + rr * FROWB + cc * 16, Kh + (size_t)rr * HD + cc * 8);
        CP_ASYNC16(uV[0] + rr * FROWB + cc * 16, Vh + (size_t)rr * HD + cc * 8);
    }
    CP_COMMIT();

    uint32_t aoff = (uint32_t)((wid * 16 + (lane & 15)) * FROWB + ((lane >> 4) & 1) * 16);
    uint32_t boff = (uint32_t)((lane & 15) * FROWB + ((lane >> 4) & 1) * 16);
    uint32_t voff = (uint32_t)(((lane & 7) + ((lane >> 3) & 1) * 8) * FROWB
                               + ((lane >> 4) & 1) * 16);

    float ls0 = 0.f, ls1 = 0.f;
    float oacc[8][4];
    #pragma unroll
    for (int nt = 0; nt < 8; nt++)
        #pragma unroll
        for (int e = 0; e < 4; e++) oacc[nt][e] = 0.f;

    int prow0 = wid * 16 + (lane >> 2);
    int pcol  = 2 * (lane & 3);

    int buf = 0;
    for (int kb = 0; kb < LTOT; kb += 64) {
        CP_WAIT(0);
        __syncthreads();
        // issue next K/V tile into the other buffer (overlaps with compute)
        if (kb + 64 < LTOT) {
            int nb = buf ^ 1;
            #pragma unroll
            for (int i = 0; i < 2; i++) {
                int id = tid + i * 256;
                int rr = id >> 3, cc = id & 7;
                CP_ASYNC16(uK[nb] + rr * FROWB + cc * 16,
                           Kh + (size_t)(kb + 64 + rr) * HD + cc * 8);
                CP_ASYNC16(uV[nb] + rr * FROWB + cc * 16,
                           Vh + (size_t)(kb + 64 + rr) * HD + cc * 8);
            }
            CP_COMMIT();
        }

        // S = Q @ K^T  (per warp: 16 x 64)
        float sacc[8][4];
        #pragma unroll
        for (int nt = 0; nt < 8; nt++)
            #pragma unroll
            for (int e = 0; e < 4; e++) sacc[nt][e] = 0.f;
        #pragma unroll
        for (int ks = 0; ks < 4; ks++) {
            uint32_t af[4], bf[4][4];
            LDSM_X4(af, uQ + aoff + ks * 32);
            #pragma unroll
            for (int p = 0; p < 4; p++)
                LDSM_X4(bf[p], uK[buf] + boff + p * 16 * FROWB + ks * 32);
            #pragma unroll
            for (int nt = 0; nt < 8; nt++) {
                int p = nt >> 1, q = nt & 1;
                MMA_F16(sacc[nt], af, bf[p][q], bf[p][q + 2]);
            }
        }

        // static-max softmax: weights exp(s - 8); pack P into A-fragments
        uint32_t pf[4][4];
        float ps0 = 0.f, ps1 = 0.f;
        #pragma unroll
        for (int nt = 0; nt < 8; nt++) {
            float p00 = __expf(sacc[nt][0] - 8.f);
            float p01 = __expf(sacc[nt][1] - 8.f);
            float p10 = __expf(sacc[nt][2] - 8.f);
            float p11 = __expf(sacc[nt][3] - 8.f);
            ps0 += p00 + p01; ps1 += p10 + p11;
            int ks = nt >> 1;
            if ((nt & 1) == 0) {
                pf[ks][0] = pack_h2(p00, p01);
                pf[ks][1] = pack_h2(p10, p11);
            } else {
                pf[ks][2] = pack_h2(p00, p01);
                pf[ks][3] = pack_h2(p10, p11);
            }
        }
        ps0 += __shfl_xor_sync(0xffffffffu, ps0, 1);
        ps0 += __shfl_xor_sync(0xffffffffu, ps0, 2);
        ps1 += __shfl_xor_sync(0xffffffffu, ps1, 1);
        ps1 += __shfl_xor_sync(0xffffffffu, ps1, 2);
        ls0 += ps0;
        ls1 += ps1;

        // O += P @ V  (P from registers; V via ldmatrix.trans)
        #pragma unroll
        for (int ks = 0; ks < 4; ks++) {
            uint32_t bf[4][4];
            #pragma unroll
            for (int p = 0; p < 4; p++)
                LDSM_X4_T(bf[p], uV[buf] + voff + ks * 16 * FROWB + p * 32);
            #pragma unroll
            for (int nt = 0; nt < 8; nt++) {
                int p = nt >> 1, q = nt & 1;
                MMA_F16(oacc[nt], pf[ks], bf[p][2 * q], bf[p][2 * q + 1]);
            }
        }
        buf ^= 1;
    }

    float inv0 = 1.f / ls0, inv1 = 1.f / ls1;
    int r0 = qb + prow0, r1 = r0 + 8;
    #pragma unroll
    for (int nt = 0; nt < 8; nt++) {
        int col = h * HD + nt * 8 + pcol;
        *(__half2*)(O + (size_t)r0 * HID + col) =
            __floats2half2_rn(oacc[nt][0] * inv0, oacc[nt][1] * inv0);
        *(__half2*)(O + (size_t)r1 * HID + col) =
            __floats2half2_rn(oacc[nt][2] * inv1, oacc[nt][3] * inv1);
    }
}

// ---------------- launch ---------------------------------------------------
extern "C" void kernel_launch(void* const* d_in, const int* in_sizes, int n_in,
                              void* d_out, int out_size)
{
    const float* img   = (const float*)d_in[0];
    const float* txt   = (const float*)d_in[1];
    const float* pe    = (const float*)d_in[2];
    const float* vec   = (const float*)d_in[3];
    const float* imw   = (const float*)d_in[4];
    const float* imb   = (const float*)d_in[5];
    const float* tmw   = (const float*)d_in[6];
    const float* tmb   = (const float*)d_in[7];
    const float* iqkvw = (const float*)d_in[8];
    const float* iqkvb = (const float*)d_in[9];
    const float* iqs   = (const float*)d_in[10];
    const float* iks   = (const float*)d_in[11];
    const float* projw = (const float*)d_in[12];
    const float* projb = (const float*)d_in[13];
    const float* tqkvw = (const float*)d_in[14];
    const float* tqkvb = (const float*)d_in[15];
    const float* tqs   = (const float*)d_in[16];
    const float* tks   = (const float*)d_in[17];
    const float* w1    = (const float*)d_in[18];
    const float* b1    = (const float*)d_in[19];
    const float* w2    = (const float*)d_in[20];
    const float* b2    = (const float*)d_in[21];

    float *mod, *img2, *w2part;
    __half *imgm, *txtm, *qi, *qt, *q, *k, *v, *attn, *ln2, *mlp;
    __half *wt_iqkv, *wt_tqkv, *wt_proj, *wt_w1, *wt_w2;
    cudaGetSymbolAddress((void**)&mod,  g_mod);
    cudaGetSymbolAddress((void**)&imgm, g_imgm);
    cudaGetSymbolAddress((void**)&txtm, g_txtm);
    cudaGetSymbolAddress((void**)&qi,   g_qkv_img);
    cudaGetSymbolAddress((void**)&qt,   g_qkv_txt);
    cudaGetSymbolAddress((void**)&q,    g_q);
    cudaGetSymbolAddress((void**)&k,    g_k);
    cudaGetSymbolAddress((void**)&v,    g_v);
    cudaGetSymbolAddress((void**)&attn, g_attn);
    cudaGetSymbolAddress((void**)&img2, g_img2);
    cudaGetSymbolAddress((void**)&ln2,  g_ln2);
    cudaGetSymbolAddress((void**)&mlp,  g_mlp);
    cudaGetSymbolAddress((void**)&w2part, g_w2part);
    cudaGetSymbolAddress((void**)&wt_iqkv, g_wt_iqkv);
    cudaGetSymbolAddress((void**)&wt_tqkv, g_wt_tqkv);
    cudaGetSymbolAddress((void**)&wt_proj, g_wt_proj);
    cudaGetSymbolAddress((void**)&wt_w1,   g_wt_w1);
    cudaGetSymbolAddress((void**)&wt_w2,   g_wt_w2);

    cudaFuncSetAttribute(flash_f16, cudaFuncAttributeMaxDynamicSharedMemorySize, FL_SMEM);
    cudaFuncSetAttribute(qkv_gemm,            cudaFuncAttributeMaxDynamicSharedMemorySize, MM_SMEM);
    cudaFuncSetAttribute(w2_gemm,             cudaFuncAttributeMaxDynamicSharedMemorySize, MM_SMEM);
    cudaFuncSetAttribute(mma_gemm<1, __half>, cudaFuncAttributeMaxDynamicSharedMemorySize, MM_SMEM);
    cudaFuncSetAttribute(mma_gemm<2, float>,  cudaFuncAttributeMaxDynamicSharedMemorySize, MM_SMEM);

    // 0) weight transposes -> fp16 [N,K] (single launch)
    transpose_all<<<7680, 256>>>(iqkvw, tqkvw, projw, w1, w2,
                                 wt_iqkv, wt_tqkv, wt_proj, wt_w1, wt_w2);
    // 1) modulation vectors
    mod_kernel<<<96, 128>>>(vec, imw, imb, tmw, tmb, mod);
    // 2) LN + modulate (img + txt, one launch)
    ln_mod2_kernel<<<LI + LT, 256>>>(img, txt, mod, imgm, txtm);
    // 3) QKV GEMMs (img + txt merged in one launch)
    { dim3 g(24, 18); qkv_gemm<<<g, 256, MM_SMEM>>>(imgm, txtm, wt_iqkv, wt_tqkv,
                                                    iqkvb, tqkvb, qi, qt); }
    // 4) rms-norm + rope + head layout (fp16)
    build_qkv_kernel<<<LTOT, 256>>>(qi, qt, iqs, iks, tqs, tks, pe, q, k, v);
    // 5) attention (fp16 flash, img queries only, BQ=128)
    { dim3 g(LI / 128, NHEAD);
      flash_f16<<<g, 256, FL_SMEM>>>(q, k, v, attn); }
    // 6) proj + gated residual (img rows only) -> fp32
    { dim3 g(8, 16); mma_gemm<2, float><<<g, 256, MM_SMEM>>>(attn + (size_t)LT * HID, wt_proj, projb,
                                                             img, mod + 2048, img2, HID, HID); }
    // 7) LN2 + modulate -> fp16
    ln_mod_kernel<<<LI, 256>>>(img2, mod, 3072, 4096, ln2);
    // 8) MLP: w1 gemm, then split-K2 w2 + combine
    { dim3 g(32, 16); mma_gemm<1, __half><<<g, 256, MM_SMEM>>>(ln2, wt_w1, b1, nullptr, nullptr, mlp, MLPD, HID); }
    { dim3 g(8, 32);  w2_gemm<<<g, 256, MM_SMEM>>>(mlp, wt_w2, w2part); }
    w2_combine<<<LI, 256>>>(w2part, img2, b2, mod + 5120, (float*)d_out);
}

// round 15
// speedup vs baseline: 1.0316x; 1.0088x over previous
#include <cuda_runtime.h>
#include <cuda_fp16.h>
#include <cstdint>
#include <math.h>

// Problem constants
#define HID   1024
#define LT    256
#define LI    2048
#define LTOT  2304
#define NHEAD 16
#define HD    64
#define MLPD  4096

// ---------------- scratch (device globals; no cudaMalloc allowed) ----------
__device__ float  g_mod[12288];
__device__ __half g_imgm[LI * HID];
__device__ __half g_txtm[LT * HID];
__device__ __half g_qkv_img[LI * 3 * HID];
__device__ __half g_qkv_txt[LT * 3 * HID];
__device__ __half g_q[NHEAD * LTOT * HD];
__device__ __half g_k[NHEAD * LTOT * HD];
__device__ __half g_v[NHEAD * LTOT * HD];
__device__ __half g_attn[LTOT * HID];
__device__ float  g_img2[LI * HID];
__device__ __half g_ln2[LI * HID];
__device__ __half g_mlp[LI * MLPD];
__device__ float  g_w2part[2 * LI * HID];
// transposed weights [N,K] (fp16)
__device__ __half g_wt_iqkv[3 * HID * HID];
__device__ __half g_wt_tqkv[3 * HID * HID];
__device__ __half g_wt_proj[HID * HID];
__device__ __half g_wt_w1[MLPD * HID];
__device__ __half g_wt_w2[HID * MLPD];

// ---------------- PTX helpers ----------------------------------------------
__device__ __forceinline__ uint32_t smem_u32(const void* p) {
    uint32_t a;
    asm("{ .reg .u64 t; cvta.to.shared.u64 t, %1; cvt.u32.u64 %0, t; }" : "=r"(a) : "l"(p));
    return a;
}
__device__ __forceinline__ uint32_t pack_h2(float a, float b) {
    __half2 h = __floats2half2_rn(a, b);
    return *(uint32_t*)&h;
}
#define CP_ASYNC16(dst, src) \
    asm volatile("cp.async.cg.shared.global [%0], [%1], 16;" :: "r"(dst), "l"(src))
#define CP_COMMIT() asm volatile("cp.async.commit_group;")
#define CP_WAIT(n)  asm volatile("cp.async.wait_group %0;" :: "n"(n))

#define LDSM_X4(r, a)                                                          \
    asm volatile("ldmatrix.sync.aligned.m8n8.x4.shared.b16 {%0,%1,%2,%3}, [%4];" \
        : "=r"((r)[0]), "=r"((r)[1]), "=r"((r)[2]), "=r"((r)[3]) : "r"(a))

#define LDSM_X4_T(r, a)                                                        \
    asm volatile("ldmatrix.sync.aligned.m8n8.x4.trans.shared.b16 {%0,%1,%2,%3}, [%4];" \
        : "=r"((r)[0]), "=r"((r)[1]), "=r"((r)[2]), "=r"((r)[3]) : "r"(a))

// D += A(f16) * B(f16), fp32 accumulate, m16n8k16
#define MMA_F16(d, a, b0, b1)                                                  \
    asm volatile("mma.sync.aligned.m16n8k16.row.col.f32.f16.f16.f32 "          \
        "{%0,%1,%2,%3}, {%4,%5,%6,%7}, {%8,%9}, {%0,%1,%2,%3};"                \
        : "+f"((d)[0]), "+f"((d)[1]), "+f"((d)[2]), "+f"((d)[3])               \
        : "r"((a)[0]), "r"((a)[1]), "r"((a)[2]), "r"((a)[3]),                  \
          "r"(b0), "r"(b1))

// ---------------- merged weight transpose + f16: W[K,N] -> WT[N,K] ---------
__global__ void transpose_all(
    const float* __restrict__ iqkvw, const float* __restrict__ tqkvw,
    const float* __restrict__ projw, const float* __restrict__ w1,
    const float* __restrict__ w2,
    __half* __restrict__ wt_iqkv, __half* __restrict__ wt_tqkv,
    __half* __restrict__ wt_proj, __half* __restrict__ wt_w1,
    __half* __restrict__ wt_w2)
{
    __shared__ float t[64][33];
    int b = blockIdx.x;
    const float* W; __half* WT; int K, N, nx, local;
    if (b < 1536)      { W = iqkvw; WT = wt_iqkv; K = 1024; N = 3072; nx = 96;  local = b; }
    else if (b < 3072) { W = tqkvw; WT = wt_tqkv; K = 1024; N = 3072; nx = 96;  local = b - 1536; }
    else if (b < 3584) { W = projw; WT = wt_proj; K = 1024; N = 1024; nx = 32;  local = b - 3072; }
    else if (b < 5632) { W = w1;    WT = wt_w1;   K = 1024; N = 4096; nx = 128; local = b - 3584; }
    else               { W = w2;    WT = wt_w2;   K = 4096; N = 1024; nx = 32;  local = b - 5632; }
    int n0 = (local % nx) * 32, k0 = (local / nx) * 64;
    int tid = threadIdx.x;
    int rr = tid >> 5, cc = tid & 31;
    #pragma unroll
    for (int i = 0; i < 8; i++)
        t[i * 8 + rr][cc] = W[(size_t)(k0 + i * 8 + rr) * N + n0 + cc];
    __syncthreads();
    int kk = cc * 2;
    #pragma unroll
    for (int i = 0; i < 4; i++) {
        int n = i * 8 + rr;
        __half2 hv = __floats2half2_rn(t[kk][n], t[kk + 1][n]);
        *(__half2*)(WT + (size_t)(n0 + n) * K + k0 + kk) = hv;
    }
}

// ---------------- modulation: silu(vec) @ mod_w + mod_b --------------------
__global__ void mod_kernel(const float* __restrict__ vec,
                           const float* __restrict__ imw, const float* __restrict__ imb,
                           const float* __restrict__ tmw, const float* __restrict__ tmb,
                           float* __restrict__ mod)
{
    __shared__ float sv[HID];
    int tid = threadIdx.x;
    for (int i = tid; i < HID; i += 128) {
        float x = vec[i];
        sv[i] = x / (1.f + expf(-x));
    }
    __syncthreads();
    int blk = blockIdx.x;
    bool is_img = blk < 48;
    int col = (is_img ? blk : blk - 48) * 128 + tid;
    const float* w = is_img ? imw : tmw;
    const float* b = is_img ? imb : tmb;
    float* out = mod + (is_img ? 0 : 6144);
    float a0 = 0.f, a1 = 0.f, a2 = 0.f, a3 = 0.f;
    for (int d = 0; d < HID; d += 4) {
        a0 += sv[d + 0] * w[(d + 0) * 6144 + col];
        a1 += sv[d + 1] * w[(d + 1) * 6144 + col];
        a2 += sv[d + 2] * w[(d + 2) * 6144 + col];
        a3 += sv[d + 3] * w[(d + 3) * 6144 + col];
    }
    out[col] = b[col] + ((a0 + a1) + (a2 + a3));
}

// ---------------- fused LayerNorm + modulate (fp16 output) -----------------
__device__ __forceinline__ void ln_mod_body(const float* __restrict__ xrow,
                                            const float* __restrict__ mod,
                                            int shift_off, int scale_off,
                                            __half* __restrict__ orow)
{
    __shared__ float red[2][8];
    int tid = threadIdx.x;
    float4 xv = ((const float4*)xrow)[tid];
    float s  = xv.x + xv.y + xv.z + xv.w;
    float s2 = xv.x * xv.x + xv.y * xv.y + xv.z * xv.z + xv.w * xv.w;
    #pragma unroll
    for (int o = 16; o; o >>= 1) {
        s  += __shfl_xor_sync(0xffffffffu, s,  o);
        s2 += __shfl_xor_sync(0xffffffffu, s2, o);
    }
    int warp = tid >> 5, lane = tid & 31;
    if (lane == 0) { red[0][warp] = s; red[1][warp] = s2; }
    __syncthreads();
    s = 0.f; s2 = 0.f;
    #pragma unroll
    for (int w = 0; w < 8; w++) { s += red[0][w]; s2 += red[1][w]; }
    float mean = s * (1.f / HID);
    float var  = s2 * (1.f / HID) - mean * mean;
    float rs = rsqrtf(var + 1e-6f);
    int c = tid * 4;
    float4 sc = *(const float4*)(mod + scale_off + c);
    float4 sh = *(const float4*)(mod + shift_off + c);
    *(__half2*)(orow + c)     = __floats2half2_rn((xv.x - mean) * rs * (1.f + sc.x) + sh.x,
                                                  (xv.y - mean) * rs * (1.f + sc.y) + sh.y);
    *(__half2*)(orow + c + 2) = __floats2half2_rn((xv.z - mean) * rs * (1.f + sc.z) + sh.z,
                                                  (xv.w - mean) * rs * (1.f + sc.w) + sh.w);
}

__global__ void ln_mod_kernel(const float* __restrict__ x,
                              const float* __restrict__ mod,
                              int shift_off, int scale_off,
                              __half* __restrict__ out)
{
    int row = blockIdx.x;
    ln_mod_body(x + (size_t)row * HID, mod, shift_off, scale_off,
                out + (size_t)row * HID);
}

__global__ void ln_mod2_kernel(const float* __restrict__ img,
                               const float* __restrict__ txt,
                               const float* __restrict__ mod,
                               __half* __restrict__ imgm,
                               __half* __restrict__ txtm)
{
    int row = blockIdx.x;
    if (row < LI)
        ln_mod_body(img + (size_t)row * HID, mod, 0, 1024,
                    imgm + (size_t)row * HID);
    else {
        int r = row - LI;
        ln_mod_body(txt + (size_t)r * HID, mod, 6144, 7168,
                    txtm + (size_t)r * HID);
    }
}

// ---------------- fp16 mma GEMM body: C[M,N] = A[M,K] @ BT[N,K]^T ----------
__device__ __forceinline__ float gelu_tanh(float x)
{
    return 0.5f * x * (1.f + tanhf(0.7978845608028654f * (x + 0.044715f * x * x * x)));
}

#define ROWH 144                       // bytes per padded smem row (64 halves + 16B)
#define TILEH (128 * ROWH)             // 18432 B per tile
#define MM_SMEM (6 * TILEH)            // 3 stages x (A,B) = 110592 B

__device__ __forceinline__ void mm_load_tile(uint32_t sbase, const __half* __restrict__ g,
                                             int ld, int k0)
{
    int tid = threadIdx.x;
    #pragma unroll
    for (int i = 0; i < 4; i++) {
        int id = tid + i * 256;
        int r = id >> 3, c = id & 7;
        uint32_t dst = sbase + r * ROWH + c * 16;
        const __half* src = g + (size_t)r * ld + k0 + c * 8;
        CP_ASYNC16(dst, src);
    }
}

template <int EPI, typename OT>
__device__ __forceinline__ void gemm_body(
    const __half* __restrict__ A, const __half* __restrict__ BT,
    const float* __restrict__ bias, const float* __restrict__ res,
    const float* __restrict__ gate, OT* __restrict__ C,
    int N, int K, int lda, int ldb, int row0, int col0, char* smem)
{
    uint32_t su = smem_u32(smem);
    uint32_t sA[3] = { su,             su + 2 * TILEH, su + 4 * TILEH };
    uint32_t sB[3] = { su + TILEH,     su + 3 * TILEH, su + 5 * TILEH };

    int tid = threadIdx.x;
    int wid = tid >> 5, lane = tid & 31;
    int warp_m = wid & 3, warp_n = wid >> 2;
    const __half* Ab = A + (size_t)row0 * lda;
    const __half* Bb = BT + (size_t)col0 * ldb;

    float acc[2][8][4];
    #pragma unroll
    for (int mt = 0; mt < 2; mt++)
        #pragma unroll
        for (int nt = 0; nt < 8; nt++)
            #pragma unroll
            for (int e = 0; e < 4; e++) acc[mt][nt][e] = 0.f;

    uint32_t aoff = (uint32_t)((warp_m * 32 + (lane & 15)) * ROWH + ((lane >> 4) & 1) * 16);
    uint32_t boff = (uint32_t)((warp_n * 64 + (lane & 15)) * ROWH + ((lane >> 4) & 1) * 16);

    int T = K >> 6;
    mm_load_tile(sA[0], Ab, lda, 0);
    mm_load_tile(sB[0], Bb, ldb, 0);
    CP_COMMIT();
    if (T > 1) {
        mm_load_tile(sA[1], Ab, lda, 64);
        mm_load_tile(sB[1], Bb, ldb, 64);
    }
    CP_COMMIT();

    int buf = 0;
    for (int t = 0; t < T; t++) {
        if (t + 1 < T) { CP_WAIT(1); } else { CP_WAIT(0); }
        __syncthreads();
        if (t + 2 < T) {
            int nb = (buf + 2) % 3;
            mm_load_tile(sA[nb], Ab, lda, (t + 2) * 64);
            mm_load_tile(sB[nb], Bb, ldb, (t + 2) * 64);
            CP_COMMIT();
        }

        uint32_t Abase = sA[buf] + aoff;
        uint32_t Bbase = sB[buf] + boff;
        #pragma unroll
        for (int ks = 0; ks < 4; ks++) {
            uint32_t af[2][4], bf[4][4];
            LDSM_X4(af[0], Abase + ks * 32);
            LDSM_X4(af[1], Abase + 16 * ROWH + ks * 32);
            #pragma unroll
            for (int p = 0; p < 4; p++)
                LDSM_X4(bf[p], Bbase + p * 16 * ROWH + ks * 32);
            #pragma unroll
            for (int mt = 0; mt < 2; mt++)
                #pragma unroll
                for (int nt = 0; nt < 8; nt++) {
                    int p = nt >> 1, q = nt & 1;
                    MMA_F16(acc[mt][nt], af[mt], bf[p][q], bf[p][q + 2]);
                }
        }
        buf = (buf + 1) % 3;
    }

    int qr = lane >> 2, qc = (lane & 3) * 2;
    #pragma unroll
    for (int mt = 0; mt < 2; mt++) {
        int gr0 = row0 + warp_m * 32 + mt * 16 + qr;
        #pragma unroll
        for (int nt = 0; nt < 8; nt++) {
            int gc = col0 + warp_n * 64 + nt * 8 + qc;
            float2 bv = (EPI == 3) ? make_float2(0.f, 0.f)
                                   : *(const float2*)(bias + gc);
            #pragma unroll
            for (int h = 0; h < 2; h++) {
                int gr = gr0 + h * 8;
                float vx = acc[mt][nt][2 * h + 0] + bv.x;
                float vy = acc[mt][nt][2 * h + 1] + bv.y;
                if (EPI == 0) {
                    *(__half2*)((__half*)C + (size_t)gr * N + gc) =
                        __floats2half2_rn(vx, vy);
                } else if (EPI == 1) {
                    *(__half2*)((__half*)C + (size_t)gr * N + gc) =
                        __floats2half2_rn(gelu_tanh(vx), gelu_tanh(vy));
                } else if (EPI == 2) {
                    float2 rr = *(const float2*)(res + (size_t)gr * N + gc);
                    float2 gg = *(const float2*)(gate + gc);
                    float2 v = make_float2(rr.x + gg.x * vx, rr.y + gg.y * vy);
                    *(float2*)((float*)C + (size_t)gr * N + gc) = v;
                } else {
                    *(float2*)((float*)C + (size_t)gr * N + gc) =
                        make_float2(vx, vy);
                }
            }
        }
    }
}

template <int EPI, typename OT>
__global__ void __launch_bounds__(256) mma_gemm(
    const __half* __restrict__ A, const __half* __restrict__ BT,
    const float* __restrict__ bias, const float* __restrict__ res,
    const float* __restrict__ gate, OT* __restrict__ C,
    int N, int K)
{
    extern __shared__ char smem[];
    gemm_body<EPI, OT>(A, BT, bias, res, gate, C, N, K, K, K,
                       blockIdx.y * 128, blockIdx.x * 128, smem);
}

// merged QKV GEMM: blockIdx.y < 16 -> img rows, else txt rows
__global__ void __launch_bounds__(256) qkv_gemm(
    const __half* __restrict__ imgm, const __half* __restrict__ txtm,
    const __half* __restrict__ wt_i, const __half* __restrict__ wt_t,
    const float* __restrict__ bias_i, const float* __restrict__ bias_t,
    __half* __restrict__ qi, __half* __restrict__ qt)
{
    extern __shared__ char smem[];
    int by = blockIdx.y;
    if (by < 16)
        gemm_body<0, __half>(imgm, wt_i, bias_i, nullptr, nullptr, qi,
                             3 * HID, HID, HID, HID, by * 128, blockIdx.x * 128, smem);
    else
        gemm_body<0, __half>(txtm, wt_t, bias_t, nullptr, nullptr, qt,
                             3 * HID, HID, HID, HID, (by - 16) * 128, blockIdx.x * 128, smem);
}

// split-K x2 w2 GEMM: blockIdx.y < 16 -> K slice 0, else slice 1
__global__ void __launch_bounds__(256) w2_gemm(
    const __half* __restrict__ A, const __half* __restrict__ BT,
    float* __restrict__ part)
{
    extern __shared__ char smem[];
    int by = blockIdx.y;
    int slice = by >> 4;
    int row0 = (by & 15) * 128;
    gemm_body<3, float>(A + slice * 2048, BT + slice * 2048,
                        nullptr, nullptr, nullptr,
                        part + (size_t)slice * LI * HID,
                        HID, 2048, MLPD, MLPD, row0, blockIdx.x * 128, smem);
}

// combine: out = img2 + gate * (p0 + p1 + bias)
__global__ void w2_combine(const float* __restrict__ part,
                           const float* __restrict__ img2,
                           const float* __restrict__ bias,
                           const float* __restrict__ gate,
                           float* __restrict__ out)
{
    int row = blockIdx.x, tid = threadIdx.x;
    size_t base = (size_t)row * HID + tid * 4;
    float4 p0 = *(const float4*)(part + base);
    float4 p1 = *(const float4*)(part + (size_t)LI * HID + base);
    float4 rr = *(const float4*)(img2 + base);
    float4 bv = *(const float4*)(bias + tid * 4);
    float4 gg = *(const float4*)(gate + tid * 4);
    float4 o;
    o.x = rr.x + gg.x * (p0.x + p1.x + bv.x);
    o.y = rr.y + gg.y * (p0.y + p1.y + bv.y);
    o.z = rr.z + gg.z * (p0.z + p1.z + bv.z);
    o.w = rr.w + gg.w * (p0.w + p1.w + bv.w);
    *(float4*)(out + base) = o;
}

// ---------------- build q/k/v: rms-norm + rope + head layout (fp16) --------
__global__ void build_qkv_kernel(const __half* __restrict__ qkv_img,
                                 const __half* __restrict__ qkv_txt,
                                 const float* __restrict__ iqs, const float* __restrict__ iks,
                                 const float* __restrict__ tqs, const float* __restrict__ tks,
                                 const float* __restrict__ pe,
                                 __half* __restrict__ q, __half* __restrict__ k,
                                 __half* __restrict__ v)
{
    int s = blockIdx.x;
    int warp = threadIdx.x >> 5, lane = threadIdx.x & 31;
    bool is_txt = s < LT;
    const __half* src = is_txt ? (qkv_txt + (size_t)s * 3072)
                               : (qkv_img + (size_t)(s - LT) * 3072);
    for (int u = warp; u < 48; u += 8) {
        int which = u >> 4;       // 0=q 1=k 2=v
        int h = u & 15;
        const __half* base = src + which * HID + h * HD;
        float x0 = __half2float(base[2 * lane]);
        float x1 = __half2float(base[2 * lane + 1]);
        size_t didx = ((size_t)h * LTOT + s) * HD + 2 * lane;
        if (which == 2) {
            v[didx]     = __float2half_rn(x0);
            v[didx + 1] = __float2half_rn(x1);
        } else {
            float ss = x0 * x0 + x1 * x1;
            #pragma unroll
            for (int o = 16; o; o >>= 1) ss += __shfl_xor_sync(0xffffffffu, ss, o);
            float r = rsqrtf(ss * (1.f / HD) + 1e-6f);
            const float* sc = (which == 0) ? (is_txt ? tqs : iqs)
                                           : (is_txt ? tks : iks);
            x0 *= r * sc[2 * lane];
            x1 *= r * sc[2 * lane + 1];
            const float* p = pe + (size_t)s * 128 + lane * 4;
            float o0 = p[0] * x0 + p[1] * x1;
            float o1 = p[2] * x0 + p[3] * x1;
            if (which == 0) { o0 *= 0.125f; o1 *= 0.125f; }  // fold 1/sqrt(HD)
            __half* dst = (which == 0) ? q : k;
            dst[didx]     = __float2half_rn(o0);
            dst[didx + 1] = __float2half_rn(o1);
        }
    }
}

// ---------------- fp16 flash attention: BQ=128, BK=64, HD=64 ---------------
// 8 warps / 256 threads. cp.async double-buffered K/V. Static-max softmax
// (|logit| <= 8 by Cauchy-Schwarz after RMS norm + orthogonal RoPE), and P
// repacked register-to-register into mma A-fragments (no smem round trip).
#define FROWH 72                 // halves per padded smem row (64 + 8)
#define FROWB 144                // bytes per padded smem row
#define FL_SMEM ((128 + 128 + 128) * FROWB)   // Q, K[2], V[2] = 55296 B

__global__ void __launch_bounds__(256) flash_f16(
    const __half* __restrict__ Q, const __half* __restrict__ Kg,
    const __half* __restrict__ Vg, __half* __restrict__ O)
{
    extern __shared__ __half hsm[];
    __half* Qs = hsm;                        // [q][d] 128 rows
    uint32_t su = smem_u32(hsm);
    uint32_t uQ = su;
    uint32_t uK[2] = { su + 128 * FROWB, su + 192 * FROWB };
    uint32_t uV[2] = { su + 256 * FROWB, su + 320 * FROWB };

    int tid = threadIdx.x;
    int wid = tid >> 5, lane = tid & 31;
    int h = blockIdx.y;
    int qb = LT + blockIdx.x * 128;
    const __half* Qh = Q + ((size_t)h * LTOT + qb) * HD;
    const __half* Kh = Kg + (size_t)h * LTOT * HD;
    const __half* Vh = Vg + (size_t)h * LTOT * HD;

    // load Q tile [128][64]
    #pragma unroll
    for (int i = 0; i < 4; i++) {
        int f = tid + i * 256;
        int r = f >> 3, c = (f & 7) * 8;
        *(float4*)&Qs[r * FROWH + c] = *(const float4*)(Qh + (size_t)r * HD + c);
    }

    // prologue: cp.async K/V tile 0 into buf 0
    #pragma unroll
    for (int i = 0; i < 2; i++) {
        int id = tid + i * 256;
        int rr = id >> 3, cc = id & 7;
        CP_ASYNC16(uK[0] + rr * FROWB + cc * 16, Kh + (size_t)rr * HD + cc * 8);
        CP_ASYNC16(uV[0] + rr * FROWB + cc * 16, Vh + (size_t)rr * HD + cc * 8);
    }
    CP_COMMIT();

    uint32_t aoff = (uint32_t)((wid * 16 + (lane & 15)) * FROWB + ((lane >> 4) & 1) * 16);
    uint32_t boff = (uint32_t)((lane & 15) * FROWB + ((lane >> 4) & 1) * 16);
    uint32_t voff = (uint32_t)(((lane & 7) + ((lane >> 3) & 1) * 8) * FROWB
                               + ((lane >> 4) & 1) * 16);

    float ls0 = 0.f, ls1 = 0.f;
    float oacc[8][4];
    #pragma unroll
    for (int nt = 0; nt < 8; nt++)
        #pragma unroll
        for (int e = 0; e < 4; e++) oacc[nt][e] = 0.f;

    int prow0 = wid * 16 + (lane >> 2);
    int pcol  = 2 * (lane & 3);

    int buf = 0;
    for (int kb = 0; kb < LTOT; kb += 64) {
        CP_WAIT(0);
        __syncthreads();
        // issue next K/V tile into the other buffer (overlaps with compute)
        if (kb + 64 < LTOT) {
            int nb = buf ^ 1;
            #pragma unroll
            for (int i = 0; i < 2; i++) {
                int id = tid + i * 256;
                int rr = id >> 3, cc = id & 7;
                CP_ASYNC16(uK[nb] + rr * FROWB + cc * 16,
                           Kh + (size_t)(kb + 64 + rr) * HD + cc * 8);
                CP_ASYNC16(uV[nb] + rr * FROWB + cc * 16,
                           Vh + (size_t)(kb + 64 + rr) * HD + cc * 8);
            }
            CP_COMMIT();
        }

        // S = Q @ K^T  (per warp: 16 x 64)
        float sacc[8][4];
        #pragma unroll
        for (int nt = 0; nt < 8; nt++)
            #pragma unroll
            for (int e = 0; e < 4; e++) sacc[nt][e] = 0.f;
        #pragma unroll
        for (int ks = 0; ks < 4; ks++) {
            uint32_t af[4], bf[4][4];
            LDSM_X4(af, uQ + aoff + ks * 32);
            #pragma unroll
            for (int p = 0; p < 4; p++)
                LDSM_X4(bf[p], uK[buf] + boff + p * 16 * FROWB + ks * 32);
            #pragma unroll
            for (int nt = 0; nt < 8; nt++) {
                int p = nt >> 1, q = nt & 1;
                MMA_F16(sacc[nt], af, bf[p][q], bf[p][q + 2]);
            }
        }

        // static-max softmax: weights exp(s - 8); pack P into A-fragments
        uint32_t pf[4][4];
        float ps0 = 0.f, ps1 = 0.f;
        #pragma unroll
        for (int nt = 0; nt < 8; nt++) {
            float p00 = __expf(sacc[nt][0] - 8.f);
            float p01 = __expf(sacc[nt][1] - 8.f);
            float p10 = __expf(sacc[nt][2] - 8.f);
            float p11 = __expf(sacc[nt][3] - 8.f);
            ps0 += p00 + p01; ps1 += p10 + p11;
            int ks = nt >> 1;
            if ((nt & 1) == 0) {
                pf[ks][0] = pack_h2(p00, p01);
                pf[ks][1] = pack_h2(p10, p11);
            } else {
                pf[ks][2] = pack_h2(p00, p01);
                pf[ks][3] = pack_h2(p10, p11);
            }
        }
        ps0 += __shfl_xor_sync(0xffffffffu, ps0, 1);
        ps0 += __shfl_xor_sync(0xffffffffu, ps0, 2);
        ps1 += __shfl_xor_sync(0xffffffffu, ps1, 1);
        ps1 += __shfl_xor_sync(0xffffffffu, ps1, 2);
        ls0 += ps0;
        ls1 += ps1;

        // O += P @ V  (P from registers; V via ldmatrix.trans)
        #pragma unroll
        for (int ks = 0; ks < 4; ks++) {
            uint32_t bf[4][4];
            #pragma unroll
            for (int p = 0; p < 4; p++)
                LDSM_X4_T(bf[p], uV[buf] + voff + ks * 16 * FROWB + p * 32);
            #pragma unroll
            for (int nt = 0; nt < 8; nt++) {
                int p = nt >> 1, q = nt & 1;
                MMA_F16(oacc[nt], pf[ks], bf[p][2 * q], bf[p][2 * q + 1]);
            }
        }
        buf ^= 1;
    }

    float inv0 = 1.f / ls0, inv1 = 1.f / ls1;
    int r0 = qb + prow0, r1 = r0 + 8;
    #pragma unroll
    for (int nt = 0; nt < 8; nt++) {
        int col = h * HD + nt * 8 + pcol;
        *(__half2*)(O + (size_t)r0 * HID + col) =
            __floats2half2_rn(oacc[nt][0] * inv0, oacc[nt][1] * inv0);
        *(__half2*)(O + (size_t)r1 * HID + col) =
            __floats2half2_rn(oacc[nt][2] * inv1, oacc[nt][3] * inv1);
    }
}

// ---------------- launch ---------------------------------------------------
extern "C" void kernel_launch(void* const* d_in, const int* in_sizes, int n_in,
                              void* d_out, int out_size)
{
    const float* img   = (const float*)d_in[0];
    const float* txt   = (const float*)d_in[1];
    const float* pe    = (const float*)d_in[2];
    const float* vec   = (const float*)d_in[3];
    const float* imw   = (const float*)d_in[4];
    const float* imb   = (const float*)d_in[5];
    const float* tmw   = (const float*)d_in[6];
    const float* tmb   = (const float*)d_in[7];
    const float* iqkvw = (const float*)d_in[8];
    const float* iqkvb = (const float*)d_in[9];
    const float* iqs   = (const float*)d_in[10];
    const float* iks   = (const float*)d_in[11];
    const float* projw = (const float*)d_in[12];
    const float* projb = (const float*)d_in[13];
    const float* tqkvw = (const float*)d_in[14];
    const float* tqkvb = (const float*)d_in[15];
    const float* tqs   = (const float*)d_in[16];
    const float* tks   = (const float*)d_in[17];
    const float* w1    = (const float*)d_in[18];
    const float* b1    = (const float*)d_in[19];
    const float* w2    = (const float*)d_in[20];
    const float* b2    = (const float*)d_in[21];

    float *mod, *img2, *w2part;
    __half *imgm, *txtm, *qi, *qt, *q, *k, *v, *attn, *ln2, *mlp;
    __half *wt_iqkv, *wt_tqkv, *wt_proj, *wt_w1, *wt_w2;
    cudaGetSymbolAddress((void**)&mod,  g_mod);
    cudaGetSymbolAddress((void**)&imgm, g_imgm);
    cudaGetSymbolAddress((void**)&txtm, g_txtm);
    cudaGetSymbolAddress((void**)&qi,   g_qkv_img);
    cudaGetSymbolAddress((void**)&qt,   g_qkv_txt);
    cudaGetSymbolAddress((void**)&q,    g_q);
    cudaGetSymbolAddress((void**)&k,    g_k);
    cudaGetSymbolAddress((void**)&v,    g_v);
    cudaGetSymbolAddress((void**)&attn, g_attn);
    cudaGetSymbolAddress((void**)&img2, g_img2);
    cudaGetSymbolAddress((void**)&ln2,  g_ln2);
    cudaGetSymbolAddress((void**)&mlp,  g_mlp);
    cudaGetSymbolAddress((void**)&w2part, g_w2part);
    cudaGetSymbolAddress((void**)&wt_iqkv, g_wt_iqkv);
    cudaGetSymbolAddress((void**)&wt_tqkv, g_wt_tqkv);
    cudaGetSymbolAddress((void**)&wt_proj, g_wt_proj);
    cudaGetSymbolAddress((void**)&wt_w1,   g_wt_w1);
    cudaGetSymbolAddress((void**)&wt_w2,   g_wt_w2);

    cudaFuncSetAttribute(flash_f16, cudaFuncAttributeMaxDynamicSharedMemorySize, FL_SMEM);
    cudaFuncSetAttribute(qkv_gemm,            cudaFuncAttributeMaxDynamicSharedMemorySize, MM_SMEM);
    cudaFuncSetAttribute(w2_gemm,             cudaFuncAttributeMaxDynamicSharedMemorySize, MM_SMEM);
    cudaFuncSetAttribute(mma_gemm<1, __half>, cudaFuncAttributeMaxDynamicSharedMemorySize, MM_SMEM);
    cudaFuncSetAttribute(mma_gemm<2, float>,  cudaFuncAttributeMaxDynamicSharedMemorySize, MM_SMEM);

    // 0) weight transposes -> fp16 [N,K] (single launch)
    transpose_all<<<7680, 256>>>(iqkvw, tqkvw, projw, w1, w2,
                                 wt_iqkv, wt_tqkv, wt_proj, wt_w1, wt_w2);
    // 1) modulation vectors
    mod_kernel<<<96, 128>>>(vec, imw, imb, tmw, tmb, mod);
    // 2) LN + modulate (img + txt, one launch)
    ln_mod2_kernel<<<LI + LT, 256>>>(img, txt, mod, imgm, txtm);
    // 3) QKV GEMMs (img + txt merged in one launch)
    { dim3 g(24, 18); qkv_gemm<<<g, 256, MM_SMEM>>>(imgm, txtm, wt_iqkv, wt_tqkv,
                                                    iqkvb, tqkvb, qi, qt); }
    // 4) rms-norm + rope + head layout (fp16)
    build_qkv_kernel<<<LTOT, 256>>>(qi, qt, iqs, iks, tqs, tks, pe, q, k, v);
    // 5) attention (fp16 flash, img queries only, BQ=128)
    { dim3 g(LI / 128, NHEAD);
      flash_f16<<<g, 256, FL_SMEM>>>(q, k, v, attn); }
    // 6) proj + gated residual (img rows only) -> fp32
    { dim3 g(8, 16); mma_gemm<2, float><<<g, 256, MM_SMEM>>>(attn + (size_t)LT * HID, wt_proj, projb,
                                                             img, mod + 2048, img2, HID, HID); }
    // 7) LN2 + modulate -> fp16
    ln_mod_kernel<<<LI, 256>>>(img2, mod, 3072, 4096, ln2);
    // 8) MLP: w1 gemm, then split-K2 w2 + combine
    { dim3 g(32, 16); mma_gemm<1, __half><<<g, 256, MM_SMEM>>>(ln2, wt_w1, b1, nullptr, nullptr, mlp, MLPD, HID); }
    { dim3 g(8, 32);  w2_gemm<<<g, 256, MM_SMEM>>>(mlp, wt_w2, w2part); }
    w2_combine<<<LI, 256>>>(w2part, img2, b2, mod + 5120, (float*)d_out);
}